// round 9
// baseline (speedup 1.0000x reference)
#include <cuda_runtime.h>
#include <cstdint>

// ---------------- problem constants ----------------
#define F_NUM   104013
#define KP      104064              // padded K: 3252 * 32
#define B_ROWS  1024
#define NCOLS   312
#define NPAD    320                 // col 312 = w, 313..319 = 0

// ---------------- GEMM tiling ----------------
#define BM        32
#define BN        320               // full N per CTA
#define BK        32                // k bytes (int8) per stage
#define KT        3252              // KP / 32
#define SPLITK    5
#define TILES_PER 651               // ceil(3252/5)
#define NST       4

// stage smem: rows of 32B data + 16B pad (pitch 48 -> conflict-free ldmatrix)
#define PITCH     48
#define A_TILE    (32 * PITCH)      // 1536
#define B_TILE    (320 * PITCH)     // 15360
#define STG       (2 * A_TILE + 2 * B_TILE)   // 33792
#define SMEM_TOT  (NST * STG)       // 135168

// ---------------- device scratch ----------------
__device__ unsigned char g_x1[(size_t)B_ROWS * KP];
__device__ unsigned char g_x0[(size_t)B_ROWS * KP];
__device__ unsigned char g_v1[(size_t)NPAD * KP];   // s8 bit patterns
__device__ unsigned char g_v0[(size_t)NPAD * KP];
__device__ int           g_hi[(size_t)SPLITK * B_ROWS * NPAD];
__device__ int           g_md[(size_t)SPLITK * B_ROWS * NPAD];
__device__ int           g_lo[(size_t)SPLITK * B_ROWS * NPAD];

// ---------------- helpers ----------------
__device__ __forceinline__ unsigned smem_u32(const void* p) {
    return (unsigned)__cvta_generic_to_shared(p);
}
__device__ __forceinline__ void cpa16(unsigned dst, const void* src) {
    asm volatile("cp.async.cg.shared.global [%0], [%1], 16;\n" :: "r"(dst), "l"(src));
}
__device__ __forceinline__ void ldsm4(int* r, unsigned a) {
    asm volatile("ldmatrix.sync.aligned.m8n8.x4.shared.b16 {%0,%1,%2,%3}, [%4];"
                 : "=r"(r[0]), "=r"(r[1]), "=r"(r[2]), "=r"(r[3]) : "r"(a));
}
__device__ __forceinline__ void imma(int* c, const int* a, const int* b) {
    asm volatile("mma.sync.aligned.m16n8k32.row.col.s32.u8.s8.s32 "
                 "{%0,%1,%2,%3}, {%4,%5,%6,%7}, {%8,%9}, {%0,%1,%2,%3};"
                 : "+r"(c[0]), "+r"(c[1]), "+r"(c[2]), "+r"(c[3])
                 : "r"(a[0]), "r"(a[1]), "r"(a[2]), "r"(a[3]), "r"(b[0]), "r"(b[1]));
}

// ---------------- convert X -> u8 digit pair (x * 2^16), padded ----------------
__global__ void __launch_bounds__(256)
cvt_x(const float* __restrict__ X) {
    const int m   = blockIdx.y;
    const int kp4 = (blockIdx.x * 256 + threadIdx.x) * 4;
    if (kp4 >= KP) return;
    uchar4 d1, d0;
    unsigned char* p1 = &d1.x;
    unsigned char* p0 = &d0.x;
#pragma unroll
    for (int j = 0; j < 4; ++j) {
        const int kp = kp4 + j;
        float v = (kp < F_NUM) ? X[(size_t)m * F_NUM + kp] : 0.f;
        int q = (int)rintf(v * 65536.f);
        q = max(0, min(q, 65535));
        p1[j] = (unsigned char)(q >> 8);
        p0[j] = (unsigned char)(q & 255);
    }
    const size_t o = (size_t)m * KP + kp4;
    *reinterpret_cast<uchar4*>(g_x1 + o) = d1;
    *reinterpret_cast<uchar4*>(g_x0 + o) = d0;
}

// ---------------- convert+transpose Vcat -> [320][KP] s8 digit pair (v * 2^17) --
__global__ void __launch_bounds__(256)
cvt_v(const float* __restrict__ V, const float* __restrict__ W) {
    __shared__ unsigned char s1[32][144];
    __shared__ unsigned char s0[32][144];
    const int k0 = blockIdx.x * 128;
    const int n0 = blockIdx.y * 32;
    const int t  = threadIdx.x;
    const int j  = t & 31;      // n within tile
    const int i0 = t >> 5;      // k row base (stride 8)
#pragma unroll
    for (int p = 0; p < 16; ++p) {
        const int i = i0 + p * 8;          // k 0..127
        const int k = k0 + i, n = n0 + j;
        float v = 0.f;
        if (k < F_NUM) {
            if (n < NCOLS)       v = V[(size_t)k * NCOLS + n];
            else if (n == NCOLS) v = W[k];
        }
        int vi = (int)rintf(v * 131072.f);       // v * 2^17
        vi = max(-32768, min(vi, 32639));
        int v1 = (vi + 128) >> 8;          // [-128, 127]
        int v0 = vi - (v1 << 8);           // [-128, 127]
        s1[j][i] = (unsigned char)(v1 & 255);
        s0[j][i] = (unsigned char)(v0 & 255);
    }
    __syncthreads();
    const int r  = t >> 3;      // n row 0..31
    const int c8 = t & 7;       // 16-byte chunk
    const size_t ob = (size_t)(n0 + r) * KP + k0 + c8 * 16;
    *reinterpret_cast<uint4*>(g_v1 + ob) =
        *reinterpret_cast<const uint4*>(&s1[r][c8 * 16]);
    *reinterpret_cast<uint4*>(g_v0 + ob) =
        *reinterpret_cast<const uint4*>(&s0[r][c8 * 16]);
}

// ---------------- int8 exact 4-pass IMMA GEMM ----------------
__global__ void __launch_bounds__(256, 1)
fm_gemm() {
    extern __shared__ char smem[];
    const unsigned sbase = smem_u32(smem);
    const int t    = threadIdx.x;
    const int lane = t & 31;
    const int wid  = t >> 5;
    const int wm   = wid >> 2;     // 0..1  (16-row slice)
    const int wn   = wid & 3;      // 0..3  (80-col slice)
    const int m0   = blockIdx.x * BM;
    const int bz   = blockIdx.z;

    const int tile0 = bz * TILES_PER;
    const int T = min(TILES_PER, KT - tile0);

    int acc_hi[10][4], acc_md[10][4], acc_lo[10][4];
#pragma unroll
    for (int b = 0; b < 10; ++b)
#pragma unroll
        for (int c = 0; c < 4; ++c) {
            acc_hi[b][c] = 0; acc_md[b][c] = 0; acc_lo[b][c] = 0;
        }

    // ---- loader per-thread constants ----
    // A: 128 chunks of 16B (threads 0-127): digit = t>>6, row = (t>>1)&31, kc = t&1
    const int a_d = (t >> 6) & 1, a_r = (t >> 1) & 31, a_kc = t & 1;
    const bool a_active = (t < 128);
    const size_t a_src = (size_t)(m0 + a_r) * KP + a_kc * 16;
    const unsigned a_dst = (unsigned)(a_d * A_TILE + a_r * PITCH + a_kc * 16);
    const unsigned char* a_gp = a_d ? g_x0 : g_x1;

    auto load_stage = [&](int slot, int jt) {
        const unsigned tb = sbase + (unsigned)slot * STG;
        const size_t kel = (size_t)jt * BK;
        if (a_active) cpa16(tb + a_dst, a_gp + a_src + kel);
        // B: 1280 chunks: digit = c/640, row = (c%640)>>1, kc = c&1
#pragma unroll
        for (int i = 0; i < 5; ++i) {
            const int c = t + i * 256;
            const int d = c >= 640;
            const int cc = c - d * 640;
            const int row = cc >> 1, kc = cc & 1;
            const unsigned dst = tb + 2u * A_TILE + (unsigned)(d * B_TILE + row * PITCH + kc * 16);
            const unsigned char* gp = d ? g_v0 : g_v1;
            cpa16(dst, gp + (size_t)row * KP + kel + kc * 16);
        }
    };

    // ---- ldmatrix per-lane offsets ----
    const unsigned a_loff = (unsigned)((wm * 16 + (lane & 15)) * PITCH + (lane >> 4) * 16);
    const unsigned b_loff = (unsigned)((wn * 80 + (lane & 7) + ((lane & 16) >> 1)) * PITCH
                                       + ((lane & 8) << 1));
    const unsigned bbase = sbase + 2u * A_TILE;

    load_stage(0, tile0 + 0);
    asm volatile("cp.async.commit_group;\n");
    load_stage(1, tile0 + 1);
    asm volatile("cp.async.commit_group;\n");
    load_stage(2, tile0 + 2);
    asm volatile("cp.async.commit_group;\n");

    for (int it = 0; it < T; ++it) {
        asm volatile("cp.async.wait_group 2;\n");
        __syncthreads();

        const int j = it + 3;
        if (j < T) load_stage(j & 3, tile0 + j);
        asm volatile("cp.async.commit_group;\n");

        const unsigned tb = sbase + (unsigned)(it & 3) * STG;
        const unsigned bt = bbase + (unsigned)(it & 3) * STG;
        int a1[4], a0f[4], bq[20];
        ldsm4(a1,  tb + a_loff);
        ldsm4(a0f, tb + A_TILE + a_loff);
        // B digit 1: x1*v1 -> hi, x0*v1 -> md
#pragma unroll
        for (int p = 0; p < 5; ++p)
            ldsm4(bq + p * 4, bt + b_loff + p * 16 * PITCH);
#pragma unroll
        for (int nt = 0; nt < 10; ++nt) {
            imma(acc_hi[nt], a1,  bq + nt * 2);
            imma(acc_md[nt], a0f, bq + nt * 2);
        }
        // B digit 0: x1*v0 -> md, x0*v0 -> lo
#pragma unroll
        for (int p = 0; p < 5; ++p)
            ldsm4(bq + p * 4, bt + B_TILE + b_loff + p * 16 * PITCH);
#pragma unroll
        for (int nt = 0; nt < 10; ++nt) {
            imma(acc_md[nt], a1,  bq + nt * 2);
            imma(acc_lo[nt], a0f, bq + nt * 2);
        }
    }
    asm volatile("cp.async.wait_group 0;\n");

    // ---- store partials ----
    const int r0 = m0 + wm * 16 + (lane >> 2);
    const int c0 = wn * 80 + 2 * (lane & 3);
    const size_t pb = (size_t)bz * B_ROWS * NPAD;
#pragma unroll
    for (int nt = 0; nt < 10; ++nt) {
        const int c = c0 + nt * 8;
        const size_t o0 = pb + (size_t)r0 * NPAD + c;
        const size_t o1 = pb + (size_t)(r0 + 8) * NPAD + c;
        *reinterpret_cast<int2*>(g_hi + o0) = make_int2(acc_hi[nt][0], acc_hi[nt][1]);
        *reinterpret_cast<int2*>(g_hi + o1) = make_int2(acc_hi[nt][2], acc_hi[nt][3]);
        *reinterpret_cast<int2*>(g_md + o0) = make_int2(acc_md[nt][0], acc_md[nt][1]);
        *reinterpret_cast<int2*>(g_md + o1) = make_int2(acc_md[nt][2], acc_md[nt][3]);
        *reinterpret_cast<int2*>(g_lo + o0) = make_int2(acc_lo[nt][0], acc_lo[nt][1]);
        *reinterpret_cast<int2*>(g_lo + o1) = make_int2(acc_lo[nt][2], acc_lo[nt][3]);
    }
}

// ---------------- epilogue: rescale + FM identity ----------------
// field value = (hi*2^16 + md*2^8 + lo) * 2^-33
__global__ void __launch_bounds__(128)
fm_epilogue(const float* __restrict__ w0, float* __restrict__ out) {
    const int b = blockIdx.x;
    const int t = threadIdx.x;
    __shared__ float row[NPAD];
    __shared__ float red[128];
    __shared__ float skq[8];

    for (int c = t; c < NPAD; c += 128) {
        float hi = 0.f, md = 0.f, lo = 0.f;
#pragma unroll
        for (int s = 0; s < SPLITK; ++s) {
            const size_t o = ((size_t)(s * B_ROWS + b)) * NPAD + c;
            hi += (float)g_hi[o];
            md += (float)g_md[o];
            lo += (float)g_lo[o];
        }
        row[c] = hi * (1.f / 131072.f) + md * (1.f / 33554432.f)
               + lo * (1.f / 8589934592.f);
    }
    __syncthreads();

    float sq = 0.f;
    for (int c = t; c < NCOLS; c += 128) sq += row[c] * row[c];
    red[t] = sq;
    __syncthreads();
#pragma unroll
    for (int off = 64; off > 0; off >>= 1) {
        if (t < off) red[t] += red[t + off];
        __syncthreads();
    }
    if (t < 8) {
        float s = 0.f;
#pragma unroll
        for (int i = 0; i < 39; ++i) s += row[i * 8 + t];
        skq[t] = s * s;
    }
    __syncthreads();
    if (t == 0) {
        const float s2 = skq[0] + skq[1] + skq[2] + skq[3]
                       + skq[4] + skq[5] + skq[6] + skq[7];
        out[b] = w0[0] + row[NCOLS] + 0.5f * (s2 - red[0]);
    }
}

extern "C" void kernel_launch(void* const* d_in, const int* in_sizes, int n_in,
                              void* d_out, int out_size) {
    const float* X  = (const float*)d_in[0];   // [1024, 104013]
    const float* w0 = (const float*)d_in[1];   // [1]
    const float* W  = (const float*)d_in[2];   // [104013, 1]
    const float* V  = (const float*)d_in[3];   // [104013, 312]
    float* out = (float*)d_out;                // [1024, 1]

    cvt_x<<<dim3((KP / 4 + 255) / 256, B_ROWS), 256>>>(X);
    cvt_v<<<dim3(KP / 128, NPAD / 32), 256>>>(V, W);

    cudaFuncSetAttribute(fm_gemm, cudaFuncAttributeMaxDynamicSharedMemorySize,
                         SMEM_TOT);
    fm_gemm<<<dim3(B_ROWS / BM, 1, SPLITK), 256, SMEM_TOT>>>();
    fm_epilogue<<<B_ROWS, 128>>>(w0, out);
}

// round 11
// speedup vs baseline: 6.1388x; 6.1388x over previous
#include <cuda_runtime.h>
#include <cstdint>

// ---------------- problem constants ----------------
#define F_NUM   104013
#define B_ROWS  1024
#define NCOLS   312
#define NPAD    320                 // col 312 = w, 313..319 = 0

// ---------------- GEMM tiling ----------------
#define BM        64
#define BN        320               // full N per CTA
#define BK        32
#define KT        3251              // ceil(104013/32)
#define SPLITK    9
#define TILES_PER 362               // ceil(3251/9)
#define NST       3

// smem per stage (floats): A [64][36], B [32][328]
#define A_PITCH   36
#define B_PITCH   328
#define A_FLOATS  (64 * A_PITCH)                 // 2304
#define STG_FLOATS (A_FLOATS + 32 * B_PITCH)     // 12800
#define SMEM_TOT  (NST * STG_FLOATS * 4)         // 153600 B

// ---------------- device scratch ----------------
__device__ float g_part[(size_t)SPLITK * B_ROWS * NPAD];

// ---------------- helpers ----------------
__device__ __forceinline__ unsigned smem_u32(const void* p) {
    return (unsigned)__cvta_generic_to_shared(p);
}
__device__ __forceinline__ void cpa16(unsigned dst, const void* src, int sbytes) {
    asm volatile("cp.async.cg.shared.global [%0], [%1], 16, %2;\n"
                 :: "r"(dst), "l"(src), "r"(sbytes));
}
__device__ __forceinline__ void cpa4(unsigned dst, const void* src, int sbytes) {
    asm volatile("cp.async.ca.shared.global [%0], [%1], 4, %2;\n"
                 :: "r"(dst), "l"(src), "r"(sbytes));
}
__device__ __forceinline__ uint32_t tf32(float f) {
    uint32_t u;
    asm("cvt.rna.tf32.f32 %0, %1;" : "=r"(u) : "f"(f));
    return u;
}
__device__ __forceinline__ void mma_tf32(float* c, const uint32_t* a, const uint32_t* b) {
    asm volatile("mma.sync.aligned.m16n8k8.row.col.f32.tf32.tf32.f32 "
                 "{%0,%1,%2,%3}, {%4,%5,%6,%7}, {%8,%9}, {%0,%1,%2,%3};"
                 : "+f"(c[0]), "+f"(c[1]), "+f"(c[2]), "+f"(c[3])
                 : "r"(a[0]), "r"(a[1]), "r"(a[2]), "r"(a[3]), "r"(b[0]), "r"(b[1]));
}

// ---------------- single-pass TF32 GEMM ----------------
// D[bz][m][n] partial = X[m, ktiles(bz)] @ Vcat[k, n]   (Vcat col 312 = w)
__global__ void __launch_bounds__(256, 1)
fm_gemm(const float* __restrict__ X, const float* __restrict__ W,
        const float* __restrict__ V) {
    extern __shared__ float smem[];
    const unsigned sbase = smem_u32(smem);
    const int t    = threadIdx.x;
    const int lane = t & 31;
    const int wid  = t >> 5;
    const int wm   = wid >> 2;     // 0..1  (32-row slice)
    const int wn   = wid & 3;      // 0..3  (80-col slice)
    const int m0   = blockIdx.x * BM;
    const int bz   = blockIdx.z;

    const int tile0 = bz * TILES_PER;
    const int T = min(TILES_PER, KT - tile0);

    float acc[2][10][4];
#pragma unroll
    for (int a = 0; a < 2; ++a)
#pragma unroll
        for (int b = 0; b < 10; ++b)
#pragma unroll
            for (int c = 0; c < 4; ++c) acc[a][b][c] = 0.f;

    // ---- loader constants ----
    const int a_row = t >> 5;          // +8 per i (8 iters): rows 0..63
    const int a_k   = t & 31;
    const int b_r0  = (t >> 5) * 4;    // 4 k-rows per warp
    const int b_ln  = t & 31;

    auto load_stage = [&](int slot, int jt) {
        const unsigned tb = sbase + (unsigned)(slot * STG_FLOATS * 4);
        const int kt = jt * BK;
        // A: 64 rows x 32 floats, scalar cp.async (X rows are only 4B aligned)
#pragma unroll
        for (int i = 0; i < 8; ++i) {
            const int row = a_row + i * 8;
            const int kg  = kt + a_k;
            const int sz  = (kg < F_NUM) ? 4 : 0;
            const float* s = sz ? (X + (size_t)(m0 + row) * F_NUM + kg) : X;
            cpa4(tb + (unsigned)((row * A_PITCH + a_k) * 4), s, sz);
        }
        // B: 32 k-rows x 320 cols (+pad) as [k][n] smem
#pragma unroll
        for (int r8 = 0; r8 < 4; ++r8) {
            const int krow = b_r0 + r8;
            const int kg   = kt + krow;
            const bool kv  = (kg < F_NUM);
            const unsigned rb = tb + (unsigned)((A_FLOATS + krow * B_PITCH) * 4);
#pragma unroll
            for (int j = 0; j < 3; ++j) {
                const int c = b_ln + j * 32;            // 16B chunk id
                if (c < 78) {
                    const float* s = kv ? (V + (size_t)kg * NCOLS + c * 4) : V;
                    cpa16(rb + (unsigned)(c * 16), s, kv ? 16 : 0);
                } else if (c == 78) {
                    const float* s = kv ? (W + kg) : W;
                    cpa4(rb + 78u * 16, s, kv ? 4 : 0);
                    cpa4(rb + 78u * 16 + 4,  W, 0);
                    cpa4(rb + 78u * 16 + 8,  W, 0);
                    cpa4(rb + 78u * 16 + 12, W, 0);
                } else if (c == 79) {
                    cpa16(rb + 79u * 16, V, 0);
                }
            }
        }
    };

    load_stage(0, tile0 + 0);
    asm volatile("cp.async.commit_group;\n");
    load_stage(1, tile0 + 1);
    asm volatile("cp.async.commit_group;\n");

    const int fr = lane >> 2;     // fragment row/groupID
    const int fc = lane & 3;      // fragment col/threadID_in_group

    for (int it = 0; it < T; ++it) {
        asm volatile("cp.async.wait_group 1;\n");
        __syncthreads();

        const int j = it + 2;
        if (j < T) load_stage((it + 2) % NST, tile0 + j);
        asm volatile("cp.async.commit_group;\n");

        const float* sA = smem + (it % NST) * STG_FLOATS;
        const float* sB = sA + A_FLOATS;
#pragma unroll
        for (int kk = 0; kk < 4; ++kk) {
            // A fragments: m16k8, row-major
            uint32_t af[2][4];
#pragma unroll
            for (int mt = 0; mt < 2; ++mt) {
                const float* ap = sA + (wm * 32 + mt * 16 + fr) * A_PITCH + kk * 8 + fc;
                af[mt][0] = tf32(ap[0]);
                af[mt][1] = tf32(ap[8 * A_PITCH]);
                af[mt][2] = tf32(ap[4]);
                af[mt][3] = tf32(ap[8 * A_PITCH + 4]);
            }
            // B fragments: k8n8, col-major (n-indexed by groupID)
            uint32_t bf[10][2];
#pragma unroll
            for (int nt = 0; nt < 10; ++nt) {
                const float* bp = sB + (kk * 8 + fc) * B_PITCH + wn * 80 + nt * 8 + fr;
                bf[nt][0] = tf32(bp[0]);
                bf[nt][1] = tf32(bp[4 * B_PITCH]);
            }
#pragma unroll
            for (int mt = 0; mt < 2; ++mt)
#pragma unroll
                for (int nt = 0; nt < 10; ++nt)
                    mma_tf32(acc[mt][nt], af[mt], bf[nt]);
        }
    }
    asm volatile("cp.async.wait_group 0;\n");

    // ---- store partials ----
    const int r0 = m0 + wm * 32 + fr;
    const int c0 = wn * 80 + 2 * fc;
    float* base = g_part + (size_t)bz * B_ROWS * NPAD;
#pragma unroll
    for (int mt = 0; mt < 2; ++mt)
#pragma unroll
        for (int nt = 0; nt < 10; ++nt) {
            const int r = r0 + mt * 16, c = c0 + nt * 8;
            *reinterpret_cast<float2*>(base + (size_t)r * NPAD + c) =
                make_float2(acc[mt][nt][0], acc[mt][nt][1]);
            *reinterpret_cast<float2*>(base + (size_t)(r + 8) * NPAD + c) =
                make_float2(acc[mt][nt][2], acc[mt][nt][3]);
        }
}

// ---------------- epilogue: FM identity ----------------
__global__ void __launch_bounds__(128)
fm_epilogue(const float* __restrict__ w0, float* __restrict__ out) {
    const int b = blockIdx.x;
    const int t = threadIdx.x;
    __shared__ float row[NPAD];
    __shared__ float red[128];
    __shared__ float skq[8];

    for (int c = t; c < NPAD; c += 128) {
        float v = 0.f;
#pragma unroll
        for (int s = 0; s < SPLITK; ++s)
            v += g_part[((size_t)(s * B_ROWS + b)) * NPAD + c];
        row[c] = v;
    }
    __syncthreads();

    float sq = 0.f;
    for (int c = t; c < NCOLS; c += 128) sq += row[c] * row[c];
    red[t] = sq;
    __syncthreads();
#pragma unroll
    for (int off = 64; off > 0; off >>= 1) {
        if (t < off) red[t] += red[t + off];
        __syncthreads();
    }
    if (t < 8) {
        float s = 0.f;
#pragma unroll
        for (int i = 0; i < 39; ++i) s += row[i * 8 + t];
        skq[t] = s * s;
    }
    __syncthreads();
    if (t == 0) {
        const float s2 = skq[0] + skq[1] + skq[2] + skq[3]
                       + skq[4] + skq[5] + skq[6] + skq[7];
        out[b] = w0[0] + row[NCOLS] + 0.5f * (s2 - red[0]);
    }
}

extern "C" void kernel_launch(void* const* d_in, const int* in_sizes, int n_in,
                              void* d_out, int out_size) {
    const float* X  = (const float*)d_in[0];   // [1024, 104013]
    const float* w0 = (const float*)d_in[1];   // [1]
    const float* W  = (const float*)d_in[2];   // [104013, 1]
    const float* V  = (const float*)d_in[3];   // [104013, 312]
    float* out = (float*)d_out;                // [1024, 1]

    cudaFuncSetAttribute(fm_gemm, cudaFuncAttributeMaxDynamicSharedMemorySize,
                         SMEM_TOT);
    fm_gemm<<<dim3(B_ROWS / BM, 1, SPLITK), 256, SMEM_TOT>>>(X, W, V);
    fm_epilogue<<<B_ROWS, 128>>>(w0, out);
}

// round 14
// speedup vs baseline: 7.2692x; 1.1841x over previous
#include <cuda_runtime.h>
#include <cstdint>

// ---------------- problem constants ----------------
#define F_NUM   104013
#define B_ROWS  1024
#define NCOLS   312
#define NPAD    320                 // col 312 = w, 313..319 = 0

// ---------------- GEMM tiling ----------------
#define BM        64
#define BN        320               // full N per CTA
#define BK        32
#define KT        3251              // ceil(104013/32)
#define SPLITK    9
#define TILES_PER 362               // ceil(3251/9)
#define NST       3

// smem per stage (floats): A [64][36], B [32][332]
// B_PITCH*4 must be 16B-multiple (cp.async.16 dst align); 332*4=1328 ✓
// and 2*fc*332 mod 32 = {0,24,16,8} -> conflict-free B fragment gather
#define A_PITCH   36
#define B_PITCH   332
#define A_FLOATS  (64 * A_PITCH)                 // 2304
#define STG_FLOATS (A_FLOATS + 32 * B_PITCH)     // 12928
#define SMEM_TOT  (NST * STG_FLOATS * 4)         // 155136 B

// ---------------- device scratch ----------------
__device__ float g_part[(size_t)SPLITK * B_ROWS * NPAD];

// ---------------- helpers ----------------
__device__ __forceinline__ unsigned smem_u32(const void* p) {
    return (unsigned)__cvta_generic_to_shared(p);
}
__device__ __forceinline__ void cpa16(unsigned dst, const void* src, int sbytes) {
    asm volatile("cp.async.cg.shared.global [%0], [%1], 16, %2;\n"
                 :: "r"(dst), "l"(src), "r"(sbytes));
}
__device__ __forceinline__ void cpa4(unsigned dst, const void* src, int sbytes) {
    asm volatile("cp.async.ca.shared.global [%0], [%1], 4, %2;\n"
                 :: "r"(dst), "l"(src), "r"(sbytes));
}
// pack two f32 -> f16x2 (lo = first arg, hi = second)
__device__ __forceinline__ uint32_t pkh(float lo, float hi) {
    uint32_t u;
    asm("cvt.rn.f16x2.f32 %0, %1, %2;" : "=r"(u) : "f"(hi), "f"(lo));
    return u;
}
__device__ __forceinline__ void mma_f16(float* c, const uint32_t* a, const uint32_t* b) {
    asm volatile("mma.sync.aligned.m16n8k16.row.col.f32.f16.f16.f32 "
                 "{%0,%1,%2,%3}, {%4,%5,%6,%7}, {%8,%9}, {%0,%1,%2,%3};"
                 : "+f"(c[0]), "+f"(c[1]), "+f"(c[2]), "+f"(c[3])
                 : "r"(a[0]), "r"(a[1]), "r"(a[2]), "r"(a[3]), "r"(b[0]), "r"(b[1]));
}

// ---------------- single-pass FP16 GEMM (f32 smem, in-register convert) -------
// D[bz][m][n] partial = X[m, ktiles(bz)] @ Vcat[k, n]   (Vcat col 312 = w)
__global__ void __launch_bounds__(256, 1)
fm_gemm(const float* __restrict__ X, const float* __restrict__ W,
        const float* __restrict__ V) {
    extern __shared__ float smem[];
    const unsigned sbase = smem_u32(smem);
    const int t    = threadIdx.x;
    const int lane = t & 31;
    const int wid  = t >> 5;
    const int wm   = wid >> 2;     // 0..1  (32-row slice)
    const int wn   = wid & 3;      // 0..3  (80-col slice)
    const int m0   = blockIdx.x * BM;
    const int bz   = blockIdx.z;

    const int tile0 = bz * TILES_PER;
    const int T = min(TILES_PER, KT - tile0);

    float acc[2][10][4];
#pragma unroll
    for (int a = 0; a < 2; ++a)
#pragma unroll
        for (int b = 0; b < 10; ++b)
#pragma unroll
            for (int c = 0; c < 4; ++c) acc[a][b][c] = 0.f;

    // ---- loader constants ----
    const int a_row = t >> 5;          // +8 per i (8 iters): rows 0..63
    const int a_k   = t & 31;
    const int b_r0  = (t >> 5) * 4;    // 4 k-rows per warp
    const int b_ln  = t & 31;

    auto load_stage = [&](int slot, int jt) {
        const unsigned tb = sbase + (unsigned)(slot * STG_FLOATS * 4);
        const int kt = jt * BK;
        // A: 64 rows x 32 floats, scalar cp.async (X rows are only 4B aligned)
#pragma unroll
        for (int i = 0; i < 8; ++i) {
            const int row = a_row + i * 8;
            const int kg  = kt + a_k;
            const int sz  = (kg < F_NUM) ? 4 : 0;
            const float* s = sz ? (X + (size_t)(m0 + row) * F_NUM + kg) : X;
            cpa4(tb + (unsigned)((row * A_PITCH + a_k) * 4), s, sz);
        }
        // B: 32 k-rows x 320 cols (+pad) as [k][n] smem
#pragma unroll
        for (int r8 = 0; r8 < 4; ++r8) {
            const int krow = b_r0 + r8;
            const int kg   = kt + krow;
            const bool kv  = (kg < F_NUM);
            const unsigned rb = tb + (unsigned)((A_FLOATS + krow * B_PITCH) * 4);
#pragma unroll
            for (int j = 0; j < 3; ++j) {
                const int c = b_ln + j * 32;            // 16B chunk id
                if (c < 78) {
                    const float* s = kv ? (V + (size_t)kg * NCOLS + c * 4) : V;
                    cpa16(rb + (unsigned)(c * 16), s, kv ? 16 : 0);
                } else if (c == 78) {
                    const float* s = kv ? (W + kg) : W;
                    cpa4(rb + 78u * 16, s, kv ? 4 : 0);
                    cpa4(rb + 78u * 16 + 4,  W, 0);
                    cpa4(rb + 78u * 16 + 8,  W, 0);
                    cpa4(rb + 78u * 16 + 12, W, 0);
                } else if (c == 79) {
                    cpa16(rb + 79u * 16, V, 0);
                }
            }
        }
    };

    load_stage(0, tile0 + 0);
    asm volatile("cp.async.commit_group;\n");
    load_stage(1, tile0 + 1);
    asm volatile("cp.async.commit_group;\n");

    const int fr = lane >> 2;     // groupID  (rows / n-col)
    const int fc = lane & 3;      // threadID_in_group

    for (int it = 0; it < T; ++it) {
        asm volatile("cp.async.wait_group 1;\n");
        __syncthreads();

        const int j = it + 2;
        if (j < T) load_stage((it + 2) % NST, tile0 + j);
        asm volatile("cp.async.commit_group;\n");

        const float* sA = smem + (it % NST) * STG_FLOATS;
        const float* sB = sA + A_FLOATS;
#pragma unroll
        for (int kk = 0; kk < 2; ++kk) {
            // A frags: m16k16 row-major; a0=(fr,2fc..+1) a1=(fr+8,..) a2=(fr,+8) a3=(fr+8,+8)
            uint32_t af[2][4];
#pragma unroll
            for (int mt = 0; mt < 2; ++mt) {
                const float* ap = sA + (wm * 32 + mt * 16 + fr) * A_PITCH + kk * 16 + 2 * fc;
                const float2 v0 = *reinterpret_cast<const float2*>(ap);
                const float2 v1 = *reinterpret_cast<const float2*>(ap + 8 * A_PITCH);
                const float2 v2 = *reinterpret_cast<const float2*>(ap + 8);
                const float2 v3 = *reinterpret_cast<const float2*>(ap + 8 * A_PITCH + 8);
                af[mt][0] = pkh(v0.x, v0.y);
                af[mt][1] = pkh(v1.x, v1.y);
                af[mt][2] = pkh(v2.x, v2.y);
                af[mt][3] = pkh(v3.x, v3.y);
            }
            // B frags: k16n8 col-major; b0 = k{2fc,2fc+1} col fr; b1 = k{2fc+8,2fc+9}
            uint32_t bf[10][2];
#pragma unroll
            for (int nt = 0; nt < 10; ++nt) {
                const float* bp = sB + (kk * 16 + 2 * fc) * B_PITCH + wn * 80 + nt * 8 + fr;
                bf[nt][0] = pkh(bp[0],            bp[B_PITCH]);
                bf[nt][1] = pkh(bp[8 * B_PITCH],  bp[9 * B_PITCH]);
            }
#pragma unroll
            for (int mt = 0; mt < 2; ++mt)
#pragma unroll
                for (int nt = 0; nt < 10; ++nt)
                    mma_f16(acc[mt][nt], af[mt], bf[nt]);
        }
    }
    asm volatile("cp.async.wait_group 0;\n");

    // ---- store partials ----
    const int r0 = m0 + wm * 32 + fr;
    const int c0 = wn * 80 + 2 * fc;
    float* base = g_part + (size_t)bz * B_ROWS * NPAD;
#pragma unroll
    for (int mt = 0; mt < 2; ++mt)
#pragma unroll
        for (int nt = 0; nt < 10; ++nt) {
            const int r = r0 + mt * 16, c = c0 + nt * 8;
            *reinterpret_cast<float2*>(base + (size_t)r * NPAD + c) =
                make_float2(acc[mt][nt][0], acc[mt][nt][1]);
            *reinterpret_cast<float2*>(base + (size_t)(r + 8) * NPAD + c) =
                make_float2(acc[mt][nt][2], acc[mt][nt][3]);
        }
}

// ---------------- epilogue: FM identity ----------------
__global__ void __launch_bounds__(128)
fm_epilogue(const float* __restrict__ w0, float* __restrict__ out) {
    const int b = blockIdx.x;
    const int t = threadIdx.x;
    __shared__ float row[NPAD];
    __shared__ float red[128];
    __shared__ float skq[8];

    for (int c = t; c < NPAD; c += 128) {
        float v = 0.f;
#pragma unroll
        for (int s = 0; s < SPLITK; ++s)
            v += g_part[((size_t)(s * B_ROWS + b)) * NPAD + c];
        row[c] = v;
    }
    __syncthreads();

    float sq = 0.f;
    for (int c = t; c < NCOLS; c += 128) sq += row[c] * row[c];
    red[t] = sq;
    __syncthreads();
#pragma unroll
    for (int off = 64; off > 0; off >>= 1) {
        if (t < off) red[t] += red[t + off];
        __syncthreads();
    }
    if (t < 8) {
        float s = 0.f;
#pragma unroll
        for (int i = 0; i < 39; ++i) s += row[i * 8 + t];
        skq[t] = s * s;
    }
    __syncthreads();
    if (t == 0) {
        const float s2 = skq[0] + skq[1] + skq[2] + skq[3]
                       + skq[4] + skq[5] + skq[6] + skq[7];
        out[b] = w0[0] + row[NCOLS] + 0.5f * (s2 - red[0]);
    }
}

extern "C" void kernel_launch(void* const* d_in, const int* in_sizes, int n_in,
                              void* d_out, int out_size) {
    const float* X  = (const float*)d_in[0];   // [1024, 104013]
    const float* w0 = (const float*)d_in[1];   // [1]
    const float* W  = (const float*)d_in[2];   // [104013, 1]
    const float* V  = (const float*)d_in[3];   // [104013, 312]
    float* out = (float*)d_out;                // [1024, 1]

    cudaFuncSetAttribute(fm_gemm, cudaFuncAttributeMaxDynamicSharedMemorySize,
                         SMEM_TOT);
    fm_gemm<<<dim3(B_ROWS / BM, 1, SPLITK), 256, SMEM_TOT>>>(X, W, V);
    fm_epilogue<<<B_ROWS, 128>>>(w0, out);
}

// round 16
// speedup vs baseline: 10.3013x; 1.4171x over previous
#include <cuda_runtime.h>
#include <cuda_fp16.h>
#include <cstdint>

// ---------------- problem constants ----------------
#define F_NUM   104013
#define KP      104064              // padded K: 3252*32 = 813*128
#define B_ROWS  1024
#define NCOLS   312
#define NPAD    320                 // col 312 = w, 313..319 = 0

// ---------------- GEMM tiling ----------------
#define BM        64
#define BN        320               // full N per CTA
#define BK        32
#define KT        3252              // KP / 32
#define SPLITK    18
#define TILES_PER 181               // ceil(3252/18)
#define NST       3

// smem per stage: A f32 [64][36] + B f16 [320 rows][80 B pitch (64B data)]
#define A_PITCH   36
#define A_FLOATS  (64 * A_PITCH)                  // 2304 floats = 9216 B
#define B_PITCHB  80                              // bytes per n-row
#define B_BYTES   (320 * B_PITCHB)                // 25600 B
#define STG_BYTES (A_FLOATS * 4 + B_BYTES)        // 34816 B
#define SMEM_TOT  (NST * STG_BYTES)               // 104448 B  (x2 CTA = 208896)

// ---------------- device scratch ----------------
__device__ unsigned short g_vh[(size_t)NPAD * KP];     // f16 bits, n-major
__device__ float          g_part[(size_t)SPLITK * B_ROWS * NPAD];

// ---------------- helpers ----------------
__device__ __forceinline__ unsigned smem_u32(const void* p) {
    return (unsigned)__cvta_generic_to_shared(p);
}
__device__ __forceinline__ void cpa16(unsigned dst, const void* src) {
    asm volatile("cp.async.cg.shared.global [%0], [%1], 16;\n" :: "r"(dst), "l"(src));
}
__device__ __forceinline__ void cpa4(unsigned dst, const void* src, int sbytes) {
    asm volatile("cp.async.ca.shared.global [%0], [%1], 4, %2;\n"
                 :: "r"(dst), "l"(src), "r"(sbytes));
}
__device__ __forceinline__ uint32_t pkh(float lo, float hi) {
    uint32_t u;
    asm("cvt.rn.f16x2.f32 %0, %1, %2;" : "=r"(u) : "f"(hi), "f"(lo));
    return u;
}
__device__ __forceinline__ void ldsm4(uint32_t* r, unsigned a) {
    asm volatile("ldmatrix.sync.aligned.m8n8.x4.shared.b16 {%0,%1,%2,%3}, [%4];"
                 : "=r"(r[0]), "=r"(r[1]), "=r"(r[2]), "=r"(r[3]) : "r"(a));
}
__device__ __forceinline__ void mma_f16(float* c, const uint32_t* a,
                                        uint32_t b0, uint32_t b1) {
    asm volatile("mma.sync.aligned.m16n8k16.row.col.f32.f16.f16.f32 "
                 "{%0,%1,%2,%3}, {%4,%5,%6,%7}, {%8,%9}, {%0,%1,%2,%3};"
                 : "+f"(c[0]), "+f"(c[1]), "+f"(c[2]), "+f"(c[3])
                 : "r"(a[0]), "r"(a[1]), "r"(a[2]), "r"(a[3]), "r"(b0), "r"(b1));
}

// ---------------- convert+transpose Vcat -> [320][KP] f16, n-major ----------
__global__ void __launch_bounds__(256)
cvt_v(const float* __restrict__ V, const float* __restrict__ W) {
    __shared__ unsigned short sh[32][136];
    const int k0 = blockIdx.x * 128;
    const int n0 = blockIdx.y * 32;
    const int t  = threadIdx.x;
    const int j  = t & 31;      // n within tile
    const int i0 = t >> 5;      // k row base (stride 8)
#pragma unroll
    for (int p = 0; p < 16; ++p) {
        const int i = i0 + p * 8;          // k 0..127
        const int k = k0 + i, n = n0 + j;
        float v = 0.f;
        if (k < F_NUM) {
            if (n < NCOLS)       v = V[(size_t)k * NCOLS + n];
            else if (n == NCOLS) v = W[k];
        }
        const __half h = __float2half(v);
        sh[j][i] = *reinterpret_cast<const unsigned short*>(&h);
    }
    __syncthreads();
    const int r  = t >> 3;      // n row 0..31
    const int c8 = t & 7;
#pragma unroll
    for (int q = 0; q < 2; ++q) {
        const int chunk = c8 + q * 8;       // 0..15 (8 f16 each)
        const size_t ob = (size_t)(n0 + r) * KP + k0 + chunk * 8;
        *reinterpret_cast<uint4*>(g_vh + ob) =
            *reinterpret_cast<const uint4*>(&sh[r][chunk * 8]);
    }
}

// ---------------- single-pass FP16 GEMM (A: f32 stream, B: f16 ldmatrix) -----
__global__ void __launch_bounds__(256, 2)
fm_gemm(const float* __restrict__ X) {
    extern __shared__ float smem[];
    const unsigned sbase = smem_u32(smem);
    const int t    = threadIdx.x;
    const int lane = t & 31;
    const int wid  = t >> 5;
    const int wm   = wid >> 2;     // 0..1  (32-row slice)
    const int wn   = wid & 3;      // 0..3  (80-col slice)
    const int m0   = blockIdx.x * BM;
    const int bz   = blockIdx.z;

    const int tile0 = bz * TILES_PER;
    const int T = min(TILES_PER, KT - tile0);

    float acc[2][10][4];
#pragma unroll
    for (int a = 0; a < 2; ++a)
#pragma unroll
        for (int b = 0; b < 10; ++b)
#pragma unroll
            for (int c = 0; c < 4; ++c) acc[a][b][c] = 0.f;

    // ---- loader constants ----
    const int a_row = t >> 5;          // +8 per i: rows 0..63
    const int a_k   = t & 31;
    const int b_row = t >> 2;          // +64 per i: rows 0..319 (5 iters: 64/iter)
    const int b_kc  = t & 3;           // 16B chunk within 64B row

    auto load_stage = [&](int slot, int jt) {
        const unsigned tb = sbase + (unsigned)(slot * STG_BYTES);
        const int kt = jt * BK;
        // A: 64 rows x 32 floats, scalar cp.async (X rows 4B-aligned only)
#pragma unroll
        for (int i = 0; i < 8; ++i) {
            const int row = a_row + i * 8;
            const int kg  = kt + a_k;
            const int sz  = (kg < F_NUM) ? 4 : 0;
            const float* s = sz ? (X + (size_t)(m0 + row) * F_NUM + kg) : X;
            cpa4(tb + (unsigned)((row * A_PITCH + a_k) * 4), s, sz);
        }
        // B: 320 n-rows x 64B (32 f16), vector cp.async from g_vh
        const unsigned bb = tb + (unsigned)(A_FLOATS * 4);
#pragma unroll
        for (int i = 0; i < 5; ++i) {
            const int row = b_row + i * 64;
            cpa16(bb + (unsigned)(row * B_PITCHB + b_kc * 16),
                  g_vh + (size_t)row * KP + kt + b_kc * 8);
        }
    };

    load_stage(0, tile0 + 0);
    asm volatile("cp.async.commit_group;\n");
    load_stage(1, tile0 + 1);
    asm volatile("cp.async.commit_group;\n");

    const int fr = lane >> 2;     // groupID
    const int fc = lane & 3;      // threadID_in_group
    // ldmatrix B per-lane offset (R6-validated n-major layout)
    const unsigned b_loff = (unsigned)((wn * 80 + (lane & 7) + ((lane & 16) >> 1)) * B_PITCHB
                                       + ((lane & 8) << 1));

    for (int it = 0; it < T; ++it) {
        asm volatile("cp.async.wait_group 1;\n");
        __syncthreads();

        const int j = it + 2;
        if (j < T) load_stage((it + 2) % NST, tile0 + j);
        asm volatile("cp.async.commit_group;\n");

        const float* sA = smem + (it % NST) * (STG_BYTES / 4);
        const unsigned bt = sbase + (unsigned)((it % NST) * STG_BYTES) + A_FLOATS * 4u;
#pragma unroll
        for (int kk = 0; kk < 2; ++kk) {
            // A frags: f32 smem, packed to f16 in-register
            uint32_t af[2][4];
#pragma unroll
            for (int mt = 0; mt < 2; ++mt) {
                const float* ap = sA + (wm * 32 + mt * 16 + fr) * A_PITCH + kk * 16 + 2 * fc;
                const float2 v0 = *reinterpret_cast<const float2*>(ap);
                const float2 v1 = *reinterpret_cast<const float2*>(ap + 8 * A_PITCH);
                const float2 v2 = *reinterpret_cast<const float2*>(ap + 8);
                const float2 v3 = *reinterpret_cast<const float2*>(ap + 8 * A_PITCH + 8);
                af[mt][0] = pkh(v0.x, v0.y);
                af[mt][1] = pkh(v1.x, v1.y);
                af[mt][2] = pkh(v2.x, v2.y);
                af[mt][3] = pkh(v3.x, v3.y);
            }
            // B frags via ldmatrix: each x4 covers n16 x k16 -> 2 n-tiles
#pragma unroll
            for (int p = 0; p < 5; ++p) {
                uint32_t bq[4];
                ldsm4(bq, bt + b_loff + (unsigned)(p * 16 * B_PITCHB + kk * 32));
#pragma unroll
                for (int mt = 0; mt < 2; ++mt) {
                    mma_f16(acc[mt][2 * p],     af[mt], bq[0], bq[1]);
                    mma_f16(acc[mt][2 * p + 1], af[mt], bq[2], bq[3]);
                }
            }
        }
    }
    asm volatile("cp.async.wait_group 0;\n");

    // ---- store partials ----
    const int r0 = m0 + wm * 32 + fr;
    const int c0 = wn * 80 + 2 * fc;
    float* base = g_part + (size_t)bz * B_ROWS * NPAD;
#pragma unroll
    for (int mt = 0; mt < 2; ++mt)
#pragma unroll
        for (int nt = 0; nt < 10; ++nt) {
            const int r = r0 + mt * 16, c = c0 + nt * 8;
            *reinterpret_cast<float2*>(base + (size_t)r * NPAD + c) =
                make_float2(acc[mt][nt][0], acc[mt][nt][1]);
            *reinterpret_cast<float2*>(base + (size_t)(r + 8) * NPAD + c) =
                make_float2(acc[mt][nt][2], acc[mt][nt][3]);
        }
}

// ---------------- epilogue: FM identity ----------------
__global__ void __launch_bounds__(128)
fm_epilogue(const float* __restrict__ w0, float* __restrict__ out) {
    const int b = blockIdx.x;
    const int t = threadIdx.x;
    __shared__ float row[NPAD];
    __shared__ float red[128];
    __shared__ float skq[8];

    for (int c = t; c < NPAD; c += 128) {
        float v = 0.f;
#pragma unroll
        for (int s = 0; s < SPLITK; ++s)
            v += g_part[((size_t)(s * B_ROWS + b)) * NPAD + c];
        row[c] = v;
    }
    __syncthreads();

    float sq = 0.f;
    for (int c = t; c < NCOLS; c += 128) sq += row[c] * row[c];
    red[t] = sq;
    __syncthreads();
#pragma unroll
    for (int off = 64; off > 0; off >>= 1) {
        if (t < off) red[t] += red[t + off];
        __syncthreads();
    }
    if (t < 8) {
        float s = 0.f;
#pragma unroll
        for (int i = 0; i < 39; ++i) s += row[i * 8 + t];
        skq[t] = s * s;
    }
    __syncthreads();
    if (t == 0) {
        const float s2 = skq[0] + skq[1] + skq[2] + skq[3]
                       + skq[4] + skq[5] + skq[6] + skq[7];
        out[b] = w0[0] + row[NCOLS] + 0.5f * (s2 - red[0]);
    }
}

extern "C" void kernel_launch(void* const* d_in, const int* in_sizes, int n_in,
                              void* d_out, int out_size) {
    const float* X  = (const float*)d_in[0];   // [1024, 104013]
    const float* w0 = (const float*)d_in[1];   // [1]
    const float* W  = (const float*)d_in[2];   // [104013, 1]
    const float* V  = (const float*)d_in[3];   // [104013, 312]
    float* out = (float*)d_out;                // [1024, 1]

    cvt_v<<<dim3(KP / 128, NPAD / 32), 256>>>(V, W);

    cudaFuncSetAttribute(fm_gemm, cudaFuncAttributeMaxDynamicSharedMemorySize,
                         SMEM_TOT);
    fm_gemm<<<dim3(B_ROWS / BM, 1, SPLITK), 256, SMEM_TOT>>>(X);
    fm_epilogue<<<B_ROWS, 128>>>(w0, out);
}

// round 17
// speedup vs baseline: 12.4716x; 1.2107x over previous
#include <cuda_runtime.h>
#include <cuda_fp16.h>
#include <cstdint>

// ---------------- problem constants ----------------
#define F_NUM   104013
#define KP      104064              // padded K: 3252*32
#define B_ROWS  1024
#define NCOLS   312
#define NPAD    320                 // col 312 = w, 313..319 = 0

// ---------------- GEMM tiling ----------------
#define BM        64
#define BN        320               // full N per CTA
#define BK        32
#define KT        3252              // KP / 32
#define SPLITK    18
#define TILES_PER 181               // ceil(3252/18)
#define NST       3

// smem per stage: A f32 [64][36] + B f16 k-major [32 k][328 f16 = 656 B pitch]
#define A_PITCH   36
#define A_FLOATS  (64 * A_PITCH)                  // 2304 floats = 9216 B
#define B_PITCHB  656                             // bytes per k-row (640 data + 16 pad)
#define B_BYTES   (32 * B_PITCHB)                 // 20992 B
#define STG_BYTES (A_FLOATS * 4 + B_BYTES)        // 30208 B
#define SMEM_TOT  (NST * STG_BYTES)               // 90624 B (x2 CTA = 181248)

// ---------------- device scratch ----------------
__device__ unsigned short g_vh[(size_t)KP * NPAD];     // f16 bits, K-MAJOR [k][320]
__device__ float          g_part[(size_t)SPLITK * B_ROWS * NPAD];

// ---------------- helpers ----------------
__device__ __forceinline__ unsigned smem_u32(const void* p) {
    return (unsigned)__cvta_generic_to_shared(p);
}
__device__ __forceinline__ void cpa16(unsigned dst, const void* src) {
    asm volatile("cp.async.cg.shared.global [%0], [%1], 16;\n" :: "r"(dst), "l"(src));
}
__device__ __forceinline__ void cpa4(unsigned dst, const void* src, int sbytes) {
    asm volatile("cp.async.ca.shared.global [%0], [%1], 4, %2;\n"
                 :: "r"(dst), "l"(src), "r"(sbytes));
}
__device__ __forceinline__ uint32_t pkh(float lo, float hi) {
    uint32_t u;
    asm("cvt.rn.f16x2.f32 %0, %1, %2;" : "=r"(u) : "f"(hi), "f"(lo));
    return u;
}
__device__ __forceinline__ void ldsm4t(uint32_t* r, unsigned a) {
    asm volatile("ldmatrix.sync.aligned.m8n8.x4.trans.shared.b16 {%0,%1,%2,%3}, [%4];"
                 : "=r"(r[0]), "=r"(r[1]), "=r"(r[2]), "=r"(r[3]) : "r"(a));
}
__device__ __forceinline__ void mma_f16(float* c, const uint32_t* a,
                                        uint32_t b0, uint32_t b1) {
    asm volatile("mma.sync.aligned.m16n8k16.row.col.f32.f16.f16.f32 "
                 "{%0,%1,%2,%3}, {%4,%5,%6,%7}, {%8,%9}, {%0,%1,%2,%3};"
                 : "+f"(c[0]), "+f"(c[1]), "+f"(c[2]), "+f"(c[3])
                 : "r"(a[0]), "r"(a[1]), "r"(a[2]), "r"(a[3]), "r"(b0), "r"(b1));
}

// ---------------- convert Vcat -> [KP][320] f16, K-MAJOR, pure stream --------
// chunk = 4 f32 -> 4 f16 (8B). 80 chunks per k-row.
__global__ void __launch_bounds__(256)
cvt_v(const float* __restrict__ V, const float* __restrict__ W) {
    const size_t chunk = (size_t)blockIdx.x * 256 + threadIdx.x;
    if (chunk >= (size_t)KP * 80) return;
    const int k  = (int)(chunk / 80);
    const int c4 = (int)(chunk % 80);
    float4 v = make_float4(0.f, 0.f, 0.f, 0.f);
    if (k < F_NUM) {
        if (c4 < 78) {
            v = *reinterpret_cast<const float4*>(V + (size_t)k * NCOLS + c4 * 4);
        } else if (c4 == 78) {
            v.x = W[k];            // cols 312 (w), 313..315 = 0
        }                          // c4 == 79: cols 316..319 = 0
    }
    const uint32_t p0 = pkh(v.x, v.y);
    const uint32_t p1 = pkh(v.z, v.w);
    *reinterpret_cast<uint2*>(g_vh + (size_t)k * NPAD + c4 * 4) = make_uint2(p0, p1);
}

// ---------------- single-pass FP16 GEMM (A: f32 stream, B: ldmatrix.trans) ---
__global__ void __launch_bounds__(256, 2)
fm_gemm(const float* __restrict__ X) {
    extern __shared__ float smem[];
    const unsigned sbase = smem_u32(smem);
    const int t    = threadIdx.x;
    const int lane = t & 31;
    const int wid  = t >> 5;
    const int wm   = wid >> 2;     // 0..1  (32-row slice)
    const int wn   = wid & 3;      // 0..3  (80-col slice)
    const int m0   = blockIdx.x * BM;
    const int bz   = blockIdx.z;

    const int tile0 = bz * TILES_PER;
    const int T = min(TILES_PER, KT - tile0);

    float acc[2][10][4];
#pragma unroll
    for (int a = 0; a < 2; ++a)
#pragma unroll
        for (int b = 0; b < 10; ++b)
#pragma unroll
            for (int c = 0; c < 4; ++c) acc[a][b][c] = 0.f;

    // ---- loader constants ----
    const int a_row = t >> 5;          // +8 per i: rows 0..63
    const int a_k   = t & 31;
    const int b_row = t >> 3;          // k-row 0..31
    const int b_kc  = t & 7;           // +8 per i: 16B chunks 0..39

    auto load_stage = [&](int slot, int jt) {
        const unsigned tb = sbase + (unsigned)(slot * STG_BYTES);
        const int kt = jt * BK;
        // A: 64 rows x 32 floats, scalar cp.async (X rows 4B-aligned only)
#pragma unroll
        for (int i = 0; i < 8; ++i) {
            const int row = a_row + i * 8;
            const int kg  = kt + a_k;
            const int sz  = (kg < F_NUM) ? 4 : 0;
            const float* s = sz ? (X + (size_t)(m0 + row) * F_NUM + kg) : X;
            cpa4(tb + (unsigned)((row * A_PITCH + a_k) * 4), s, sz);
        }
        // B: 32 k-rows x 640B data, vector cp.async from k-major g_vh (no guards)
        const unsigned bb = tb + (unsigned)(A_FLOATS * 4);
#pragma unroll
        for (int i = 0; i < 5; ++i) {
            const int kc = b_kc + i * 8;
            cpa16(bb + (unsigned)(b_row * B_PITCHB + kc * 16),
                  g_vh + (size_t)(kt + b_row) * NPAD + kc * 8);
        }
    };

    load_stage(0, tile0 + 0);
    asm volatile("cp.async.commit_group;\n");
    load_stage(1, tile0 + 1);
    asm volatile("cp.async.commit_group;\n");

    const int fr = lane >> 2;     // groupID
    const int fc = lane & 3;      // threadID_in_group
    // ldmatrix.trans per-lane offset: k-row = lane&15, +16B (8 f16 n) for lanes 16+
    const unsigned b_loff = (unsigned)((lane & 15) * B_PITCHB + (lane & 16));

    for (int it = 0; it < T; ++it) {
        asm volatile("cp.async.wait_group 1;\n");
        __syncthreads();

        const int j = it + 2;
        if (j < T) load_stage((it + 2) % NST, tile0 + j);
        asm volatile("cp.async.commit_group;\n");

        const float* sA = smem + (it % NST) * (STG_BYTES / 4);
        const unsigned bt = sbase + (unsigned)((it % NST) * STG_BYTES) + A_FLOATS * 4u;
#pragma unroll
        for (int kk = 0; kk < 2; ++kk) {
            // A frags: f32 smem, packed to f16 in-register
            uint32_t af[2][4];
#pragma unroll
            for (int mt = 0; mt < 2; ++mt) {
                const float* ap = sA + (wm * 32 + mt * 16 + fr) * A_PITCH + kk * 16 + 2 * fc;
                const float2 v0 = *reinterpret_cast<const float2*>(ap);
                const float2 v1 = *reinterpret_cast<const float2*>(ap + 8 * A_PITCH);
                const float2 v2 = *reinterpret_cast<const float2*>(ap + 8);
                const float2 v3 = *reinterpret_cast<const float2*>(ap + 8 * A_PITCH + 8);
                af[mt][0] = pkh(v0.x, v0.y);
                af[mt][1] = pkh(v1.x, v1.y);
                af[mt][2] = pkh(v2.x, v2.y);
                af[mt][3] = pkh(v3.x, v3.y);
            }
            // B frags via ldmatrix.trans from k-major smem:
            // x4 covers k16 x n16 -> (b0,b1) of 2 n-tiles
#pragma unroll
            for (int p = 0; p < 5; ++p) {
                uint32_t bq[4];
                ldsm4t(bq, bt + b_loff
                           + (unsigned)(kk * 16 * B_PITCHB + (wn * 80 + p * 16) * 2));
#pragma unroll
                for (int mt = 0; mt < 2; ++mt) {
                    mma_f16(acc[mt][2 * p],     af[mt], bq[0], bq[1]);
                    mma_f16(acc[mt][2 * p + 1], af[mt], bq[2], bq[3]);
                }
            }
        }
    }
    asm volatile("cp.async.wait_group 0;\n");

    // ---- store partials ----
    const int r0 = m0 + wm * 32 + fr;
    const int c0 = wn * 80 + 2 * fc;
    float* base = g_part + (size_t)bz * B_ROWS * NPAD;
#pragma unroll
    for (int mt = 0; mt < 2; ++mt)
#pragma unroll
        for (int nt = 0; nt < 10; ++nt) {
            const int r = r0 + mt * 16, c = c0 + nt * 8;
            *reinterpret_cast<float2*>(base + (size_t)r * NPAD + c) =
                make_float2(acc[mt][nt][0], acc[mt][nt][1]);
            *reinterpret_cast<float2*>(base + (size_t)(r + 8) * NPAD + c) =
                make_float2(acc[mt][nt][2], acc[mt][nt][3]);
        }
}

// ---------------- epilogue: FM identity ----------------
__global__ void __launch_bounds__(128)
fm_epilogue(const float* __restrict__ w0, float* __restrict__ out) {
    const int b = blockIdx.x;
    const int t = threadIdx.x;
    __shared__ float row[NPAD];
    __shared__ float red[128];
    __shared__ float skq[8];

    for (int c = t; c < NPAD; c += 128) {
        float v = 0.f;
#pragma unroll
        for (int s = 0; s < SPLITK; ++s)
            v += g_part[((size_t)(s * B_ROWS + b)) * NPAD + c];
        row[c] = v;
    }
    __syncthreads();

    float sq = 0.f;
    for (int c = t; c < NCOLS; c += 128) sq += row[c] * row[c];
    red[t] = sq;
    __syncthreads();
#pragma unroll
    for (int off = 64; off > 0; off >>= 1) {
        if (t < off) red[t] += red[t + off];
        __syncthreads();
    }
    if (t < 8) {
        float s = 0.f;
#pragma unroll
        for (int i = 0; i < 39; ++i) s += row[i * 8 + t];
        skq[t] = s * s;
    }
    __syncthreads();
    if (t == 0) {
        const float s2 = skq[0] + skq[1] + skq[2] + skq[3]
                       + skq[4] + skq[5] + skq[6] + skq[7];
        out[b] = w0[0] + row[NCOLS] + 0.5f * (s2 - red[0]);
    }
}

extern "C" void kernel_launch(void* const* d_in, const int* in_sizes, int n_in,
                              void* d_out, int out_size) {
    const float* X  = (const float*)d_in[0];   // [1024, 104013]
    const float* w0 = (const float*)d_in[1];   // [1]
    const float* W  = (const float*)d_in[2];   // [104013, 1]
    const float* V  = (const float*)d_in[3];   // [104013, 312]
    float* out = (float*)d_out;                // [1024, 1]

    const long long nchunk = (long long)KP * 80;
    cvt_v<<<(unsigned)((nchunk + 255) / 256), 256>>>(V, W);

    cudaFuncSetAttribute(fm_gemm, cudaFuncAttributeMaxDynamicSharedMemorySize,
                         SMEM_TOT);
    fm_gemm<<<dim3(B_ROWS / BM, 1, SPLITK), 256, SMEM_TOT>>>(X);
    fm_epilogue<<<B_ROWS, 128>>>(w0, out);
}